// round 9
// baseline (speedup 1.0000x reference)
#include <cuda_runtime.h>

#define B_SZ 16384
#define H    256
#define H3   768
#define NSTEP 50
#define PAD  36
#define BM   32
#define NTHR 512

typedef unsigned long long ull;

// Scratch (no allocations allowed): gz = zc@Wih[:260] + bih, and h ping-pong.
__device__ __align__(16) float g_gz[B_SZ * H3];   // 48 MB
__device__ __align__(16) float g_hA[B_SZ * H];    // 16 MB
__device__ __align__(16) float g_hB[B_SZ * H];    // 16 MB

__device__ __forceinline__ ull dup2(float v) {
    ull r; asm("mov.b64 %0, {%1, %1};" : "=l"(r) : "f"(v)); return r;
}
__device__ __forceinline__ void ffma2(ull &acc, ull a, ull b) {
    asm("fma.rn.f32x2 %0, %1, %2, %0;" : "+l"(acc) : "l"(a), "l"(b));
}
__device__ __forceinline__ float2 unpk(ull v) {
    float2 r; asm("mov.b64 {%0, %1}, %2;" : "=f"(r.x), "=f"(r.y) : "l"(v)); return r;
}
__device__ __forceinline__ float sigf(float x) { return 1.f / (1.f + __expf(-x)); }

// ---------------------------------------------------------------------------
// Kernel 1: per-row precompute.
//   gz  = zc @ Wih[0:260,:] + bih          -> g_gz   [B,768]
//   h0  = zc @ Wi + bi                     -> g_hA   [B,256]
//   nn  = relu(zc @ Wn1 + bn1) @ Wn2 + bn2 -> out0   [B,49]
// Block: 32 batch rows, 512 threads, thread tile = 8 rows x 2 cols (f32x2).
// ---------------------------------------------------------------------------
__global__ void __launch_bounds__(NTHR) pre_kernel(
    const float* __restrict__ z,   const float* __restrict__ cond,
    const float* __restrict__ Wn1, const float* __restrict__ bn1,
    const float* __restrict__ Wn2, const float* __restrict__ bn2,
    const float* __restrict__ Wi,  const float* __restrict__ bi,
    const float* __restrict__ Wih, const float* __restrict__ bih,
    float* __restrict__ out0)
{
    extern __shared__ float smf[];
    float* zcT = smf;               // [260][PAD]
    float* nnT = zcT + 260 * PAD;   // [256][PAD]
    const int b0  = blockIdx.x * BM;
    const int tid = threadIdx.x;

    for (int idx = tid; idx < BM * 260; idx += NTHR) {
        int k = idx % 260, r = idx / 260;
        float v = (k < 256) ? z[(b0 + r) * 256 + k] : cond[(b0 + r) * 4 + (k - 256)];
        zcT[k * PAD + r] = v;
    }
    __syncthreads();

    const int jp = tid & 127, rg = tid >> 7;
    const int j0 = jp * 2, r0 = rg * 8;

    for (int pass = 0; pass < 5; ++pass) {
        const float* W; const float* bias; int ld, cb;
        if (pass < 3)       { W = Wih; bias = bih; ld = H3; cb = pass * 256; }
        else if (pass == 3) { W = Wi;  bias = bi;  ld = H;  cb = 0; }
        else                { W = Wn1; bias = bn1; ld = H;  cb = 0; }
        ull acc[4][2] = {};
        #pragma unroll 2
        for (int k = 0; k < 260; ++k) {
            float2 w = *(const float2*)(W + k * ld + cb + j0);
            ull w0 = dup2(w.x), w1 = dup2(w.y);
            const float* xr = zcT + k * PAD + r0;
            ull x01 = *(const ull*)(xr);
            ull x23 = *(const ull*)(xr + 2);
            ull x45 = *(const ull*)(xr + 4);
            ull x67 = *(const ull*)(xr + 6);
            ffma2(acc[0][0], x01, w0); ffma2(acc[0][1], x01, w1);
            ffma2(acc[1][0], x23, w0); ffma2(acc[1][1], x23, w1);
            ffma2(acc[2][0], x45, w0); ffma2(acc[2][1], x45, w1);
            ffma2(acc[3][0], x67, w0); ffma2(acc[3][1], x67, w1);
        }
        float bv0 = bias[cb + j0], bv1 = bias[cb + j0 + 1];
        #pragma unroll
        for (int p = 0; p < 4; ++p) {
            float2 a0 = unpk(acc[p][0]);
            float2 a1 = unpk(acc[p][1]);
            #pragma unroll
            for (int rr = 0; rr < 2; ++rr) {
                int r = r0 + 2 * p + rr;
                float v0 = (rr ? a0.y : a0.x) + bv0;
                float v1 = (rr ? a1.y : a1.x) + bv1;
                if (pass < 3) {
                    float2 o; o.x = v0; o.y = v1;
                    *(float2*)(g_gz + (b0 + r) * H3 + cb + j0) = o;
                } else if (pass == 3) {
                    float2 o; o.x = v0; o.y = v1;
                    *(float2*)(g_hA + (b0 + r) * H + j0) = o;
                } else {
                    nnT[(j0    ) * PAD + r] = fmaxf(v0, 0.f);
                    nnT[(j0 + 1) * PAD + r] = fmaxf(v1, 0.f);
                }
            }
        }
    }
    __syncthreads();

    for (int idx = tid; idx < BM * 49; idx += NTHR) {
        int row = idx / 49, o = idx % 49;
        float acc = bn2[o];
        #pragma unroll 8
        for (int k = 0; k < 256; ++k)
            acc = fmaf(nnT[k * PAD + row], Wn2[k * 49 + o], acc);
        out0[(b0 + row) * 49 + o] = acc;
    }
}

// ---------------------------------------------------------------------------
// Kernel 2: one GRU step (launched 50x).
//   gh = h @ Whh (+bhh at gate time), gi = gz + prev @ Wih[260:289]
//   n-gate recurrent part kept separate (r * h_n before adding i_n).
//   Fused heads: type logits + sigmoid(param preds).
// ---------------------------------------------------------------------------
__global__ void __launch_bounds__(NTHR) step_kernel(
    const float* __restrict__ target,
    const float* __restrict__ Wih, const float* __restrict__ Whh,
    const float* __restrict__ bhh,
    const float* __restrict__ Wt,  const float* __restrict__ bt,
    const float* __restrict__ Wp,  const float* __restrict__ bp,
    float* __restrict__ out1, float* __restrict__ out2, int t)
{
    extern __shared__ float smf[];
    float* hT  = smf;               // [256][PAD]  h_in transposed
    float* pT  = hT + 256 * PAD;    // [32][PAD]   prev features transposed
    float* hnT = pT + 32 * PAD;     // [256][PAD]  h_new transposed (for heads)
    const float* hin  = (t & 1) ? g_hB : g_hA;
    float*       hout = (t & 1) ? g_hA : g_hB;
    const int b0  = blockIdx.x * BM;
    const int tid = threadIdx.x;

    for (int idx = tid; idx < BM * 256; idx += NTHR) {
        int k = idx & 255, r = idx >> 8;
        hT[k * PAD + r] = hin[(b0 + r) * 256 + k];
    }
    for (int idx = tid; idx < BM * 32; idx += NTHR) {
        int kp = idx & 31, r = idx >> 5;
        float v = 0.f;
        if (t > 0 && kp < 29) v = target[((b0 + r) * NSTEP + (t - 1)) * 29 + kp];
        pT[kp * PAD + r] = v;
    }
    __syncthreads();

    const int jp = tid & 127, rg = tid >> 7;
    const int j0 = jp * 2, r0 = rg * 8;

    ull aR[4][2] = {}, aZ[4][2] = {}, aNh[4][2] = {}, aNi[4][2] = {};

    // gh accumulation: K = 256 over Whh (r,z,n columns j, j+256, j+512)
    #pragma unroll 2
    for (int k = 0; k < 256; ++k) {
        const float* wb = Whh + k * H3 + j0;
        float2 wr = *(const float2*)(wb);
        float2 wz = *(const float2*)(wb + 256);
        float2 wn = *(const float2*)(wb + 512);
        ull wr0 = dup2(wr.x), wr1 = dup2(wr.y);
        ull wz0 = dup2(wz.x), wz1 = dup2(wz.y);
        ull wn0 = dup2(wn.x), wn1 = dup2(wn.y);
        const float* hr = hT + k * PAD + r0;
        ull h01 = *(const ull*)(hr);
        ull h23 = *(const ull*)(hr + 2);
        ull h45 = *(const ull*)(hr + 4);
        ull h67 = *(const ull*)(hr + 6);
        ffma2(aR[0][0], h01, wr0);  ffma2(aR[0][1], h01, wr1);
        ffma2(aR[1][0], h23, wr0);  ffma2(aR[1][1], h23, wr1);
        ffma2(aR[2][0], h45, wr0);  ffma2(aR[2][1], h45, wr1);
        ffma2(aR[3][0], h67, wr0);  ffma2(aR[3][1], h67, wr1);
        ffma2(aZ[0][0], h01, wz0);  ffma2(aZ[0][1], h01, wz1);
        ffma2(aZ[1][0], h23, wz0);  ffma2(aZ[1][1], h23, wz1);
        ffma2(aZ[2][0], h45, wz0);  ffma2(aZ[2][1], h45, wz1);
        ffma2(aZ[3][0], h67, wz0);  ffma2(aZ[3][1], h67, wz1);
        ffma2(aNh[0][0], h01, wn0); ffma2(aNh[0][1], h01, wn1);
        ffma2(aNh[1][0], h23, wn0); ffma2(aNh[1][1], h23, wn1);
        ffma2(aNh[2][0], h45, wn0); ffma2(aNh[2][1], h45, wn1);
        ffma2(aNh[3][0], h67, wn0); ffma2(aNh[3][1], h67, wn1);
    }

    // prev-feature part of gi: K = 29 over Wih rows 260..288 (n part separate)
    #pragma unroll 1
    for (int kp = 0; kp < 29; ++kp) {
        const float* wb = Wih + (260 + kp) * H3 + j0;
        float2 wr = *(const float2*)(wb);
        float2 wz = *(const float2*)(wb + 256);
        float2 wn = *(const float2*)(wb + 512);
        ull wr0 = dup2(wr.x), wr1 = dup2(wr.y);
        ull wz0 = dup2(wz.x), wz1 = dup2(wz.y);
        ull wn0 = dup2(wn.x), wn1 = dup2(wn.y);
        const float* xr = pT + kp * PAD + r0;
        ull x01 = *(const ull*)(xr);
        ull x23 = *(const ull*)(xr + 2);
        ull x45 = *(const ull*)(xr + 4);
        ull x67 = *(const ull*)(xr + 6);
        ffma2(aR[0][0], x01, wr0);  ffma2(aR[0][1], x01, wr1);
        ffma2(aR[1][0], x23, wr0);  ffma2(aR[1][1], x23, wr1);
        ffma2(aR[2][0], x45, wr0);  ffma2(aR[2][1], x45, wr1);
        ffma2(aR[3][0], x67, wr0);  ffma2(aR[3][1], x67, wr1);
        ffma2(aZ[0][0], x01, wz0);  ffma2(aZ[0][1], x01, wz1);
        ffma2(aZ[1][0], x23, wz0);  ffma2(aZ[1][1], x23, wz1);
        ffma2(aZ[2][0], x45, wz0);  ffma2(aZ[2][1], x45, wz1);
        ffma2(aZ[3][0], x67, wz0);  ffma2(aZ[3][1], x67, wz1);
        ffma2(aNi[0][0], x01, wn0); ffma2(aNi[0][1], x01, wn1);
        ffma2(aNi[1][0], x23, wn0); ffma2(aNi[1][1], x23, wn1);
        ffma2(aNi[2][0], x45, wn0); ffma2(aNi[2][1], x45, wn1);
        ffma2(aNi[3][0], x67, wn0); ffma2(aNi[3][1], x67, wn1);
    }

    float2 bhr = *(const float2*)(bhh + j0);
    float2 bhz = *(const float2*)(bhh + 256 + j0);
    float2 bhn = *(const float2*)(bhh + 512 + j0);

    #pragma unroll
    for (int p = 0; p < 4; ++p) {
        float2 rA0 = unpk(aR[p][0]),  rA1 = unpk(aR[p][1]);
        float2 zA0 = unpk(aZ[p][0]),  zA1 = unpk(aZ[p][1]);
        float2 nh0 = unpk(aNh[p][0]), nh1 = unpk(aNh[p][1]);
        float2 ni0 = unpk(aNi[p][0]), ni1 = unpk(aNi[p][1]);
        #pragma unroll
        for (int rr = 0; rr < 2; ++rr) {
            int r = r0 + 2 * p + rr;
            const float* gz = g_gz + (b0 + r) * H3 + j0;
            float2 gzr = *(const float2*)(gz);
            float2 gzz = *(const float2*)(gz + 256);
            float2 gzn = *(const float2*)(gz + 512);
            float sR0 = (rr ? rA0.y : rA0.x) + gzr.x + bhr.x;
            float sR1 = (rr ? rA1.y : rA1.x) + gzr.y + bhr.y;
            float sZ0 = (rr ? zA0.y : zA0.x) + gzz.x + bhz.x;
            float sZ1 = (rr ? zA1.y : zA1.x) + gzz.y + bhz.y;
            float hN0 = (rr ? nh0.y : nh0.x) + bhn.x;   // recurrent n part
            float hN1 = (rr ? nh1.y : nh1.x) + bhn.y;
            float iN0 = (rr ? ni0.y : ni0.x) + gzn.x;   // input n part
            float iN1 = (rr ? ni1.y : ni1.x) + gzn.y;
            float rg0 = sigf(sR0), rg1 = sigf(sR1);
            float zg0 = sigf(sZ0), zg1 = sigf(sZ1);
            float n0 = tanhf(iN0 + rg0 * hN0);
            float n1 = tanhf(iN1 + rg1 * hN1);
            float ho0 = hT[(j0    ) * PAD + r];
            float ho1 = hT[(j0 + 1) * PAD + r];
            float hw0 = (1.f - zg0) * n0 + zg0 * ho0;
            float hw1 = (1.f - zg1) * n1 + zg1 * ho1;
            float2 o; o.x = hw0; o.y = hw1;
            *(float2*)(hout + (b0 + r) * H + j0) = o;
            hnT[(j0    ) * PAD + r] = hw0;
            hnT[(j0 + 1) * PAD + r] = hw1;
        }
    }
    __syncthreads();

    // heads: 15 type logits + 14 sigmoid params per row
    for (int idx = tid; idx < BM * 29; idx += NTHR) {
        int row = idx / 29, o = idx % 29;
        if (o < 15) {
            float acc = bt[o];
            #pragma unroll 8
            for (int k = 0; k < 256; ++k)
                acc = fmaf(hnT[k * PAD + row], Wt[k * 15 + o], acc);
            out1[((b0 + row) * NSTEP + t) * 15 + o] = acc;
        } else {
            int oo = o - 15;
            float acc = bp[oo];
            #pragma unroll 8
            for (int k = 0; k < 256; ++k)
                acc = fmaf(hnT[k * PAD + row], Wp[k * 14 + oo], acc);
            out2[((b0 + row) * NSTEP + t) * 14 + oo] = sigf(acc);
        }
    }
}

// ---------------------------------------------------------------------------
// Kernel 3: edge head. Every ordered pair uses the SAME MLP([h,h,zc]) value,
// so compute one scalar per row and broadcast to all 2450 slots.
// ---------------------------------------------------------------------------
__global__ void __launch_bounds__(NTHR) edge_kernel(
    const float* __restrict__ z,   const float* __restrict__ cond,
    const float* __restrict__ We1, const float* __restrict__ be1,
    const float* __restrict__ We2, const float* __restrict__ be2,
    float* __restrict__ out3)
{
    extern __shared__ float smf[];
    float* xT  = smf;               // [516][PAD]  (h 0..255, zc 256..515)
    float* e1T = xT + 516 * PAD;    // [256][PAD]
    float* ev  = e1T + 256 * PAD;   // [32]
    const int b0  = blockIdx.x * BM;
    const int tid = threadIdx.x;

    for (int idx = tid; idx < BM * 516; idx += NTHR) {
        int k = idx % 516, r = idx / 516;
        float v = (k < 256) ? g_hA[(b0 + r) * 256 + k]
                : (k < 512) ? z[(b0 + r) * 256 + (k - 256)]
                            : cond[(b0 + r) * 4 + (k - 512)];
        xT[k * PAD + r] = v;
    }
    __syncthreads();

    const int jp = tid & 127, rg = tid >> 7;
    const int j0 = jp * 2, r0 = rg * 8;

    ull acc[4][2] = {};
    // k in [0,512): both h copies (x row = k & 255); k in [512,772): zc rows
    #pragma unroll 2
    for (int k = 0; k < 772; ++k) {
        int xrow = (k < 512) ? (k & 255) : (k - 256);
        float2 w = *(const float2*)(We1 + k * H + j0);
        ull w0 = dup2(w.x), w1 = dup2(w.y);
        const float* xr = xT + xrow * PAD + r0;
        ull x01 = *(const ull*)(xr);
        ull x23 = *(const ull*)(xr + 2);
        ull x45 = *(const ull*)(xr + 4);
        ull x67 = *(const ull*)(xr + 6);
        ffma2(acc[0][0], x01, w0); ffma2(acc[0][1], x01, w1);
        ffma2(acc[1][0], x23, w0); ffma2(acc[1][1], x23, w1);
        ffma2(acc[2][0], x45, w0); ffma2(acc[2][1], x45, w1);
        ffma2(acc[3][0], x67, w0); ffma2(acc[3][1], x67, w1);
    }
    float bv0 = be1[j0], bv1 = be1[j0 + 1];
    #pragma unroll
    for (int p = 0; p < 4; ++p) {
        float2 a0 = unpk(acc[p][0]), a1 = unpk(acc[p][1]);
        int r = r0 + 2 * p;
        e1T[(j0    ) * PAD + r    ] = fmaxf(a0.x + bv0, 0.f);
        e1T[(j0    ) * PAD + r + 1] = fmaxf(a0.y + bv0, 0.f);
        e1T[(j0 + 1) * PAD + r    ] = fmaxf(a1.x + bv1, 0.f);
        e1T[(j0 + 1) * PAD + r + 1] = fmaxf(a1.y + bv1, 0.f);
    }
    __syncthreads();

    if (tid < BM) {
        float a = be2[0];
        #pragma unroll 8
        for (int k = 0; k < 256; ++k)
            a = fmaf(e1T[k * PAD + tid], We2[k], a);
        ev[tid] = a;
    }
    __syncthreads();

    for (int idx = tid; idx < BM * 2450; idx += NTHR) {
        int row = idx / 2450, col = idx % 2450;
        out3[(b0 + row) * 2450 + col] = ev[row];
    }
}

// ---------------------------------------------------------------------------
extern "C" void kernel_launch(void* const* d_in, const int* in_sizes, int n_in,
                              void* d_out, int out_size)
{
    (void)in_sizes; (void)n_in; (void)out_size;
    const float* z    = (const float*)d_in[0];
    const float* cond = (const float*)d_in[1];
    const float* tgt  = (const float*)d_in[2];
    const float* Wn1  = (const float*)d_in[3];
    const float* bn1  = (const float*)d_in[4];
    const float* Wn2  = (const float*)d_in[5];
    const float* bn2  = (const float*)d_in[6];
    const float* Wi   = (const float*)d_in[7];
    const float* bi   = (const float*)d_in[8];
    const float* Wih  = (const float*)d_in[9];
    const float* Whh  = (const float*)d_in[10];
    const float* bih  = (const float*)d_in[11];
    const float* bhh  = (const float*)d_in[12];
    const float* Wt   = (const float*)d_in[13];
    const float* bt   = (const float*)d_in[14];
    const float* Wp   = (const float*)d_in[15];
    const float* bp   = (const float*)d_in[16];
    const float* We1  = (const float*)d_in[17];
    const float* be1  = (const float*)d_in[18];
    const float* We2  = (const float*)d_in[19];
    const float* be2  = (const float*)d_in[20];
    // d_in[21] = num_nodes (always MAX_NODES=50 in this problem; compile-time NSTEP)

    float* out  = (float*)d_out;
    float* out0 = out;                                  // [B, 49]
    float* out1 = out0 + (size_t)B_SZ * 49;             // [B, 50, 15]
    float* out2 = out1 + (size_t)B_SZ * NSTEP * 15;     // [B, 50, 14]
    float* out3 = out2 + (size_t)B_SZ * NSTEP * 14;     // [B, 2450]

    const int PRE_SMEM  = (260 + 256) * PAD * 4;             // 74,304 B
    const int STEP_SMEM = (256 + 32 + 256) * PAD * 4;        // 78,336 B
    const int EDGE_SMEM = (516 + 256) * PAD * 4 + BM * 4;    // 111,296 B

    cudaFuncSetAttribute(pre_kernel,  cudaFuncAttributeMaxDynamicSharedMemorySize, PRE_SMEM);
    cudaFuncSetAttribute(step_kernel, cudaFuncAttributeMaxDynamicSharedMemorySize, STEP_SMEM);
    cudaFuncSetAttribute(edge_kernel, cudaFuncAttributeMaxDynamicSharedMemorySize, EDGE_SMEM);

    dim3 grid(B_SZ / BM);
    pre_kernel<<<grid, NTHR, PRE_SMEM>>>(z, cond, Wn1, bn1, Wn2, bn2, Wi, bi, Wih, bih, out0);
    for (int t = 0; t < NSTEP; ++t)
        step_kernel<<<grid, NTHR, STEP_SMEM>>>(tgt, Wih, Whh, bhh, Wt, bt, Wp, bp, out1, out2, t);
    edge_kernel<<<grid, NTHR, EDGE_SMEM>>>(z, cond, We1, be1, We2, be2, out3);
}